// round 8
// baseline (speedup 1.0000x reference)
#include <cuda_runtime.h>

#define HW    256
#define NB    8
#define CH    64
#define HWHW  65536

// channel-wise L1 norms per batch: [NB][HW*HW], 2 MB each
__device__ float g_n1[NB * HWHW];
__device__ float g_n2[NB * HWHW];

// grid = 192 blocks x 256 threads:
//   blocks   0..127 : norm of batch i      (reads x from DRAM, writes g_n)
//   blocks 128..191 : blend of batch i-1   (reads x from L2, writes out)
__global__ void __launch_bounds__(256)
k_mixed(int i,
        const float* __restrict__ x1, const float* __restrict__ x2,
        const float* __restrict__ w,  const float* __restrict__ bias,
        float* __restrict__ out) {
    const int tid = threadIdx.x;

    if (blockIdx.x < 128) {
        // ---------------- NORM(batch i) ----------------
#if __CUDA_ARCH__ >= 900
        cudaTriggerProgrammaticLaunchCompletion();   // let kernel_{i+1} start
#endif
        if (i >= NB) return;
        const int b   = i;
        const int g   = blockIdx.x * 256 + tid;      // 0..32767
        const int arr = g >> 14;                     // 0: x1, 1: x2
        const int q4  = (g & 16383) << 2;            // pixel quad
        const float*  x    = arr ? x2 : x1;
        float*        nbuf = arr ? g_n2 : g_n1;
        const float4* p = (const float4*)(x + (size_t)b * CH * HWHW + q4);

        float4 s = make_float4(0.f, 0.f, 0.f, 0.f);
#pragma unroll 16
        for (int c = 0; c < CH; ++c) {
            const float4 a = __ldg(p + c * (HWHW / 4));
            s.x += fabsf(a.x); s.y += fabsf(a.y);
            s.z += fabsf(a.z); s.w += fabsf(a.w);
        }
        *(float4*)(nbuf + (size_t)b * HWHW + q4) = s;
    } else {
        // ---------------- BLEND(batch i-1) ----------------
#if __CUDA_ARCH__ >= 900
        cudaTriggerProgrammaticLaunchCompletion();
#endif
        if (i == 0) return;
#if __CUDA_ARCH__ >= 900
        cudaGridDependencySynchronize();             // norm(i-1) fully visible
#endif
        const int b  = i - 1;
        const int bb = blockIdx.x - 128;             // 0..63 row-tiles
        const int r0 = bb * 4;                       // 4 rows per block

        float wv[9];
#pragma unroll
        for (int k = 0; k < 9; ++k) wv[k] = w[k];
        const float bv = bias[0];

        const float* __restrict__ n1 = g_n1 + (size_t)b * HWHW;
        const float* __restrict__ n2 = g_n2 + (size_t)b * HWHW;

        // blend factors for this thread's 4 pixels (n rows are L2/L1 hits)
        float f1r[4], f2r[4];
#pragma unroll
        for (int k = 0; k < 4; ++k) {
            const int idx = tid * 4 + k;             // 0..1023 in stripe
            const int r   = r0 + (idx >> 8);
            const int cc  = idx & 255;
            float c1 = bv, c2 = bv;
#pragma unroll
            for (int di = 0; di < 3; ++di) {
                const int rr = r + di - 1;
                if (rr < 0 || rr >= HW) continue;
#pragma unroll
                for (int dj = 0; dj < 3; ++dj) {
                    const int cj = cc + dj - 1;
                    if (cj < 0 || cj >= HW) continue;
                    const float ww = wv[di * 3 + dj];
                    c1 += ww * n1[rr * HW + cj];
                    c2 += ww * n2[rr * HW + cj];
                }
            }
            const float rd = 1.0f / (c1 + c2);
            f1r[k] = c1 * rd;
            f2r[k] = c2 * rd;
        }

        // stream 64 channels; x is L2-resident (evict-first), out streaming
        const size_t base = (size_t)b * CH * HWHW + (size_t)r0 * HW;
        const float4* p1 = (const float4*)(x1 + base);
        const float4* p2 = (const float4*)(x2 + base);
        float4*       po = (float4*)(out + base);
#pragma unroll 8
        for (int c = 0; c < CH; ++c) {
            const float4 a = __ldcs(p1 + c * (HWHW / 4) + tid);
            const float4 v = __ldcs(p2 + c * (HWHW / 4) + tid);
            float4 o;
            o.x = a.x * f1r[0] + v.x * f2r[0];
            o.y = a.y * f1r[1] + v.y * f2r[1];
            o.z = a.z * f1r[2] + v.z * f2r[2];
            o.w = a.w * f1r[3] + v.w * f2r[3];
            __stcs(po + c * (HWHW / 4) + tid, o);
        }
    }
}

extern "C" void kernel_launch(void* const* d_in, const int* in_sizes, int n_in,
                              void* d_out, int out_size) {
    const float* x1   = (const float*)d_in[0];
    const float* x2   = (const float*)d_in[1];
    const float* w    = (const float*)d_in[2];
    const float* bias = (const float*)d_in[3];
    float*       out  = (float*)d_out;

    for (int i = 0; i <= NB; ++i) {
        cudaLaunchConfig_t cfg = {};
        cfg.gridDim  = dim3(192, 1, 1);
        cfg.blockDim = dim3(256, 1, 1);
        cfg.dynamicSmemBytes = 0;
        cfg.stream = (cudaStream_t)0;   // same legacy stream as <<<>>>

        cudaLaunchAttribute attr[1];
        attr[0].id = cudaLaunchAttributeProgrammaticStreamSerialization;
        attr[0].val.programmaticStreamSerializationAllowed = 1;
        cfg.attrs    = attr;
        cfg.numAttrs = 1;

        cudaError_t e = cudaLaunchKernelEx(&cfg, k_mixed, i, x1, x2, w, bias, out);
        if (e != cudaSuccess) {
            // fallback: plain serialized launch (still correct)
            k_mixed<<<192, 256>>>(i, x1, x2, w, bias, out);
        }
    }
}

// round 9
// speedup vs baseline: 2.8331x; 2.8331x over previous
#include <cuda_runtime.h>

#define HW      256
#define NB      8
#define CH      64
#define HWHW    65536
#define THREADS 1024

// smem layout (float4 units unless noted)
//   xs1   [4096]       64 KB   row r of x1, [ch][quad]
//   xs2   [4096]       64 KB   row r of x2
//   part1 [16][64]     16 KB   norm partials (channel-group x quad)
//   part2 [16][64]     16 KB
//   n1s   [3][256] f    3 KB   norm rows r-1, r, r+1
//   n2s   [3][256] f    3 KB
//   f1s   [256]    f    1 KB   blend factors
//   f2s   [256]    f    1 KB
#define SMEM_TOTAL 172032

extern __shared__ char smem[];

__device__ __forceinline__ void acc_abs(float4& s, const float4 a) {
    s.x += fabsf(a.x); s.y += fabsf(a.y); s.z += fabsf(a.z); s.w += fabsf(a.w);
}

__global__ void __launch_bounds__(THREADS, 1)
k_fused(const float* __restrict__ x1, const float* __restrict__ x2,
        const float* __restrict__ w,  const float* __restrict__ bias,
        float* __restrict__ out) {
    float4* xs1   = (float4*)smem;
    float4* xs2   = xs1 + 4096;
    float4* part1 = xs2 + 4096;
    float4* part2 = part1 + 1024;
    float*  n1s   = (float*)(part2 + 1024);
    float*  n2s   = n1s + 768;
    float*  f1s   = n2s + 768;
    float*  f2s   = f1s + 256;

    const int u  = blockIdx.x;          // 0..2047
    const int bb = u >> 8;              // batch
    const int r  = u & 255;             // row
    const int t  = threadIdx.x;
    const int g  = t >> 6;              // channel group: ch 4g..4g+3
    const int q  = t & 63;              // float4 quad within row (px 4q..4q+3)

    const size_t imgbase = (size_t)bb * CH * HWHW;   // element index of (bb, ch=0)

    // ---- norm rows r-1, r, r+1 (row r also parked in smem) ----
#pragma unroll
    for (int dr = 0; dr < 3; ++dr) {
        const int rr = r + dr - 1;
        float4 s1 = make_float4(0.f, 0.f, 0.f, 0.f);
        float4 s2 = make_float4(0.f, 0.f, 0.f, 0.f);
        if (rr >= 0 && rr < HW) {
            const float4* p1 = (const float4*)(x1 + imgbase + (size_t)rr * HW);
            const float4* p2 = (const float4*)(x2 + imgbase + (size_t)rr * HW);
#pragma unroll
            for (int j = 0; j < 4; ++j) {
                const int ch = g * 4 + j;
                const float4 a = p1[(size_t)ch * (HWHW / 4) + q];
                const float4 v = p2[(size_t)ch * (HWHW / 4) + q];
                acc_abs(s1, a);
                acc_abs(s2, v);
                if (dr == 1) {                 // own row -> smem for the blend
                    xs1[ch * 64 + q] = a;
                    xs2[ch * 64 + q] = v;
                }
            }
        }
        part1[g * 64 + q] = s1;
        part2[g * 64 + q] = s2;
        __syncthreads();

        if (t < 128) {                         // reduce 16 group-partials
            const int arr = t >> 6, qq = t & 63;
            const float4* p = arr ? part2 : part1;
            float4 s = p[qq];
#pragma unroll
            for (int k = 1; k < 16; ++k) {
                const float4 a = p[k * 64 + qq];
                s.x += a.x; s.y += a.y; s.z += a.z; s.w += a.w;
            }
            float* dst = (arr ? n2s : n1s) + dr * 256;
            ((float4*)dst)[qq] = s;
        }
        __syncthreads();
    }

    // ---- conv factors for the 256 pixels of row r ----
    if (t < 256) {
        float c1 = bias[0], c2 = bias[0];
#pragma unroll
        for (int dr = 0; dr < 3; ++dr) {       // OOR rows are zeros == zero-pad
            const float* nr1 = n1s + dr * 256;
            const float* nr2 = n2s + dr * 256;
#pragma unroll
            for (int dj = 0; dj < 3; ++dj) {
                const int cc = t + dj - 1;
                if (cc < 0 || cc >= HW) continue;
                const float ww = __ldg(w + dr * 3 + dj);
                c1 += ww * nr1[cc];
                c2 += ww * nr2[cc];
            }
        }
        const float rd = 1.0f / (c1 + c2);
        f1s[t] = c1 * rd;
        f2s[t] = c2 * rd;
    }
    __syncthreads();

    // ---- blend from smem, streaming store ----
    const size_t rb4 = (imgbase + (size_t)r * HW) >> 2;   // f4 index of (bb,ch0,r)
#pragma unroll
    for (int i = 0; i < 4; ++i) {
        const int o  = i * THREADS + t;        // 0..4095
        const int ch = o >> 6;
        const int qq = o & 63;
        const float4 a  = xs1[o];
        const float4 v  = xs2[o];
        const float4 F1 = ((const float4*)f1s)[qq];
        const float4 F2 = ((const float4*)f2s)[qq];
        float4 ov;
        ov.x = a.x * F1.x + v.x * F2.x;
        ov.y = a.y * F1.y + v.y * F2.y;
        ov.z = a.z * F1.z + v.z * F2.z;
        ov.w = a.w * F1.w + v.w * F2.w;
        __stcs((float4*)out + rb4 + (size_t)ch * (HWHW / 4) + qq, ov);
    }
}

extern "C" void kernel_launch(void* const* d_in, const int* in_sizes, int n_in,
                              void* d_out, int out_size) {
    const float* x1   = (const float*)d_in[0];
    const float* x2   = (const float*)d_in[1];
    const float* w    = (const float*)d_in[2];
    const float* bias = (const float*)d_in[3];
    float*       out  = (float*)d_out;

    static bool attr_set = false;
    if (!attr_set) {
        cudaFuncSetAttribute(k_fused, cudaFuncAttributeMaxDynamicSharedMemorySize,
                             SMEM_TOTAL);
        attr_set = true;
    }
    k_fused<<<NB * HW, THREADS, SMEM_TOTAL>>>(x1, x2, w, bias, out);
}

// round 10
// speedup vs baseline: 3.4727x; 1.2258x over previous
#include <cuda_runtime.h>

#define HW      256
#define NB      8
#define CH      64
#define HWHW    65536
#define THREADS 512

__device__ __forceinline__ void acc_abs(float4& s, const float4 a) {
    s.x += fabsf(a.x); s.y += fabsf(a.y); s.z += fabsf(a.z); s.w += fabsf(a.w);
}

// smem: part[3][2][4][64] f4 (24 KB) + n[3][2][256] f (6 KB) + f1/f2 (2 KB)
__global__ void __launch_bounds__(THREADS, 2)
k_fused(const float* __restrict__ x1, const float* __restrict__ x2,
        const float* __restrict__ w,  const float* __restrict__ bias,
        float* __restrict__ out) {
    __shared__ float4 part[3][2][4][64];
    __shared__ float  nrm[3][2][HW];
    __shared__ float  f1s[HW], f2s[HW];

    const int u  = blockIdx.x;           // 0..2047
    const int bb = u >> 8;               // batch
    const int r  = u & 255;              // row
    const int t  = threadIdx.x;
    const int arr  = t >> 8;             // 0: x1, 1: x2
    const int grp  = (t >> 6) & 3;       // 16-channel group
    const int quad = t & 63;             // float4 quad (pixels 4q..4q+3)

    const size_t f4img = (size_t)bb * CH * (HWHW / 4);
    const float4* px = (const float4*)(arr ? x2 : x1) + f4img;

    // ---- one load phase: rows r-1, r+1, then r last (keeps r L1-hot) ----
    float4 acc0 = make_float4(0.f, 0.f, 0.f, 0.f);   // row r-1
    float4 acc1 = make_float4(0.f, 0.f, 0.f, 0.f);   // row r
    float4 acc2 = make_float4(0.f, 0.f, 0.f, 0.f);   // row r+1

    if (r > 0) {
        const float4* p = px + (size_t)(r - 1) * (HW / 4) + quad;
#pragma unroll
        for (int j = 0; j < 16; ++j)
            acc_abs(acc0, p[(size_t)(grp * 16 + j) * (HWHW / 4)]);
    }
    if (r < HW - 1) {
        const float4* p = px + (size_t)(r + 1) * (HW / 4) + quad;
#pragma unroll
        for (int j = 0; j < 16; ++j)
            acc_abs(acc2, p[(size_t)(grp * 16 + j) * (HWHW / 4)]);
    }
    {
        const float4* p = px + (size_t)r * (HW / 4) + quad;
#pragma unroll
        for (int j = 0; j < 16; ++j)
            acc_abs(acc1, p[(size_t)(grp * 16 + j) * (HWHW / 4)]);
    }
    part[0][arr][grp][quad] = acc0;
    part[1][arr][grp][quad] = acc1;
    part[2][arr][grp][quad] = acc2;
    __syncthreads();

    // ---- reduce 4 group-partials -> norm rows ----
    if (t < 384) {
        const int dr = t >> 7, ar = (t >> 6) & 1, qq = t & 63;
        float4 s = part[dr][ar][0][qq];
#pragma unroll
        for (int k = 1; k < 4; ++k) {
            const float4 a = part[dr][ar][k][qq];
            s.x += a.x; s.y += a.y; s.z += a.z; s.w += a.w;
        }
        ((float4*)nrm[dr][ar])[qq] = s;
    }
    __syncthreads();

    // ---- 3x3 conv factors for the 256 pixels of row r ----
    if (t < HW) {
        float c1 = __ldg(bias), c2 = c1;
#pragma unroll
        for (int dr = 0; dr < 3; ++dr) {     // OOR rows hold zeros == zero-pad
            const float* n1r = nrm[dr][0];
            const float* n2r = nrm[dr][1];
#pragma unroll
            for (int dj = 0; dj < 3; ++dj) {
                const int cc = t + dj - 1;
                if (cc < 0 || cc >= HW) continue;
                const float ww = __ldg(w + dr * 3 + dj);
                c1 += ww * n1r[cc];
                c2 += ww * n2r[cc];
            }
        }
        const float rd = 1.0f / (c1 + c2);
        f1s[t] = c1 * rd;
        f2s[t] = c2 * rd;
    }
    __syncthreads();

    // ---- blend: re-read row r (L1/L2 hit), streaming store ----
    const size_t rowf4 = f4img + (size_t)r * (HW / 4);
    const float4* p1 = (const float4*)x1 + rowf4;
    const float4* p2 = (const float4*)x2 + rowf4;
    float4*       po = (float4*)out + rowf4;
#pragma unroll
    for (int i = 0; i < 8; ++i) {
        const int idx = i * THREADS + t;     // 0..4095
        const int ch  = idx >> 6;
        const int qq  = idx & 63;
        const size_t off = (size_t)ch * (HWHW / 4) + qq;
        const float4 a  = p1[off];
        const float4 v  = p2[off];
        const float4 F1 = ((const float4*)f1s)[qq];
        const float4 F2 = ((const float4*)f2s)[qq];
        float4 o;
        o.x = a.x * F1.x + v.x * F2.x;
        o.y = a.y * F1.y + v.y * F2.y;
        o.z = a.z * F1.z + v.z * F2.z;
        o.w = a.w * F1.w + v.w * F2.w;
        __stcs(po + (size_t)ch * (HWHW / 4) + qq, o);
    }
}

extern "C" void kernel_launch(void* const* d_in, const int* in_sizes, int n_in,
                              void* d_out, int out_size) {
    const float* x1   = (const float*)d_in[0];
    const float* x2   = (const float*)d_in[1];
    const float* w    = (const float*)d_in[2];
    const float* bias = (const float*)d_in[3];
    float*       out  = (float*)d_out;

    k_fused<<<NB * HW, THREADS>>>(x1, x2, w, bias, out);
}